// round 6
// baseline (speedup 1.0000x reference)
#include <cuda_runtime.h>
#include <cfloat>
#include <cstdint>

// Problem constants
#define BV 8
#define TV 2048
#define GV 8
#define KV 1024
#define DV 128
#define MV (BV*TV)            // 16384 tokens
#define QN (MV*GV*DV)         // 16777216 quantized elements
#define NIDX (MV*GV)          // 131072 indices

// int8 screen parameters
#define XSCALE (4.5f/127.0f)
#define CSCALE (0.14f/127.0f)
#define INV_XS (127.0f/4.5f)
#define INV_CS (127.0f/0.14f)
#define INV_P  (16129.0f/1.26f)     // 1/(2*XSCALE*CSCALE)
#define VOFF   2066432              // shift so (v+VOFF) >= 0
#define TAU_HALF 640                // (0.1 / P) / 2, compared on (key>>10) values

// Scratch (static device globals)
__device__ float  g_c2[GV*KV];
__device__ int    g_cb8[GV*32*KV];   // [g][k4][n] packed int8x4 (dims 4k4..4k4+3)
__device__ int4   g_top4[NIDX];
__device__ int    g_flag[NIDX];
__device__ int    g_idx[NIDX];
__device__ double g_loss;

// ---------------- helpers ----------------
__device__ __forceinline__ uint32_t smem_to_u32(const void* p) {
    uint32_t a;
    asm("{ .reg .u64 t; cvta.to.shared.u64 t, %1; cvt.u32.u64 %0, t; }" : "=r"(a) : "l"(p));
    return a;
}
__device__ __forceinline__ void cp16(uint32_t dst, const void* src) {
    asm volatile("cp.async.cg.shared.global [%0], [%1], 16;" :: "r"(dst), "l"(src) : "memory");
}
#define CP_COMMIT() asm volatile("cp.async.commit_group;" ::: "memory")
#define CP_WAIT0()  asm volatile("cp.async.wait_group 0;" ::: "memory")

__device__ __forceinline__ int q8clip(float v, float inv, int& clip) {
    int i = __float2int_rn(v * inv);
    if (i > 127)  { i = 127;  clip = 1; }
    if (i < -127) { i = -127; clip = 1; }
    return i & 255;
}
__device__ __forceinline__ int pack4clip(float4 v, float inv, int& clip) {
    int i0 = q8clip(v.x, inv, clip), i1 = q8clip(v.y, inv, clip);
    int i2 = q8clip(v.z, inv, clip), i3 = q8clip(v.w, inv, clip);
    return i0 | (i1 << 8) | (i2 << 16) | (i3 << 24);
}

// SMEM layout for k_main (bytes)
#define SM_A8   0                    // 8192: As8[k4*64 + m]
#define SM_B    8192                 // 2 x 16384 double buffer: Bs[k4*128 + n]
#define SM_C2I  40960                // 4096: (c2i[n] + VOFF)
#define SM_CLIP 45056                // 64
#define SM_TOTAL 45120

// ---------- kernel 1: exact c2 + int8-packed codebook ----------
__global__ void k_prep(const float* __restrict__ cb) {
    if (blockIdx.x == 0 && threadIdx.x == 0) g_loss = 0.0;
    int warpid = (blockIdx.x * blockDim.x + threadIdx.x) >> 5;   // 0..2047
    int lane = threadIdx.x & 31;
    #pragma unroll
    for (int it = 0; it < 4; ++it) {
        int q = warpid * 4 + it;                                  // (g,n)
        const float4 v = *(const float4*)(cb + (size_t)q * DV + lane * 4);
        float s = v.x * v.x;
        s = fmaf(v.y, v.y, s);
        s = fmaf(v.z, v.z, s);
        s = fmaf(v.w, v.w, s);
        #pragma unroll
        for (int o = 16; o > 0; o >>= 1) s += __shfl_xor_sync(0xffffffffu, s, o);
        if (lane == 0) g_c2[q] = s;
    }
    // pack codebook: word w = ((g*32 + k4)*1024 + n)
    int gtid = blockIdx.x * blockDim.x + threadIdx.x;   // 0..65535
    #pragma unroll
    for (int it = 0; it < 4; ++it) {
        int w = gtid + it * 65536;            // 0..262143
        int n  = w & 1023;
        int k4 = (w >> 10) & 31;
        int g  = w >> 15;
        float4 v = *(const float4*)(cb + ((size_t)(g * KV + n)) * DV + k4 * 4);
        int dummy = 0;
        g_cb8[w] = pack4clip(v, INV_CS, dummy);
    }
}

// ---------- kernel 2: dp4a int8 screen, packed top-4 per token ----------
// CTA: 64 tokens x 1 group; 8 chunks of 128 codes. 128 threads (4m x 16n per thread).
__global__ void __launch_bounds__(128, 3)
k_main(const float* __restrict__ x) {
    extern __shared__ char smc[];
    int*  As8  = (int*)(smc + SM_A8);
    int*  c2is = (int*)(smc + SM_C2I);
    char* sclip = smc + SM_CLIP;
    const uint32_t sb = smem_to_u32(smc);

    const int tid = threadIdx.x;
    const int g   = blockIdx.y;
    const int m0  = blockIdx.x * 64;
    const int row4 = (tid >> 3) * 4;      // base row 0..60
    const int colb = (tid & 7) * 16;      // base col in chunk

    if (tid < 64) sclip[tid] = 0;
    __syncthreads();

    // c2i' = round(c2/P) + VOFF
    for (int i = tid; i < KV; i += 128)
        c2is[i] = __float2int_rn(g_c2[g * KV + i] * INV_P) + VOFF;

    // stage + quantize A (clip-detect per row)
    #pragma unroll
    for (int i = 0; i < 16; i++) {
        int idx = tid + i * 128;           // 0..2047
        int m  = idx & 63;
        int k4 = idx >> 6;                 // 0..31
        float4 v = *(const float4*)(x + (size_t)(m0 + m) * (GV * DV) + g * DV + k4 * 4);
        int clip = 0;
        As8[k4 * 64 + m] = pack4clip(v, INV_XS, clip);
        if (clip) sclip[m] = 1;
    }

    // prefetch B chunk 0
    const char* srcg = (const char*)(g_cb8 + g * 32 * KV);
    #pragma unroll
    for (int i = 0; i < 8; i++) {
        int idx = tid + i * 128;           // 0..1023 16B units
        int k4 = idx >> 5, n4 = idx & 31;
        cp16(sb + SM_B + k4 * 512 + n4 * 16, srcg + k4 * 4096 + n4 * 16);
    }
    CP_COMMIT();
    __syncthreads();

    // packed top-4 keys per row: ((v+VOFF)>>1)<<10 | n  (lexicographic)
    int K[4][4];
    #pragma unroll
    for (int r = 0; r < 4; r++)
        #pragma unroll
        for (int j = 0; j < 4; j++) K[r][j] = 0x7FFFFFFF;

    for (int ch = 0; ch < 8; ++ch) {
        CP_WAIT0();
        __syncthreads();   // data ready AND all warps done with prev buffer
        if (ch < 7) {
            uint32_t dst = sb + SM_B + ((ch + 1) & 1) * 16384;
            const char* src = srcg + (ch + 1) * 512;
            #pragma unroll
            for (int i = 0; i < 8; i++) {
                int idx = tid + i * 128;
                int k4 = idx >> 5, n4 = idx & 31;
                cp16(dst + k4 * 512 + n4 * 16, src + k4 * 4096 + n4 * 16);
            }
            CP_COMMIT();
        }
        const int* Bs = (const int*)(smc + SM_B + (ch & 1) * 16384);

        int acc[4][16];
        #pragma unroll
        for (int r = 0; r < 4; r++)
            #pragma unroll
            for (int c = 0; c < 16; c++) acc[r][c] = 0;

        #pragma unroll 4
        for (int k4 = 0; k4 < 32; ++k4) {
            int4 av = *(const int4*)&As8[k4 * 64 + row4];
            int a[4] = {av.x, av.y, av.z, av.w};
            const int* bp = &Bs[k4 * 128 + colb];
            int4 b0 = *(const int4*)(bp);
            int4 b1 = *(const int4*)(bp + 4);
            int4 b2 = *(const int4*)(bp + 8);
            int4 b3 = *(const int4*)(bp + 12);
            int b[16] = {b0.x, b0.y, b0.z, b0.w, b1.x, b1.y, b1.z, b1.w,
                         b2.x, b2.y, b2.z, b2.w, b3.x, b3.y, b3.z, b3.w};
            #pragma unroll
            for (int r = 0; r < 4; r++)
                #pragma unroll
                for (int c = 0; c < 16; c++)
                    acc[r][c] = __dp4a(a[r], b[c], acc[r][c]);
        }

        // epilogue: packed-key top-4 insert (n ascending)
        #pragma unroll
        for (int c = 0; c < 16; c++) {
            int n = ch * 128 + colb + c;
            int cc = c2is[n];
            #pragma unroll
            for (int r = 0; r < 4; r++) {
                int k = (((cc - acc[r][c]) >> 1) << 10) | n;
                if (k < K[r][3]) {
                    if (k < K[r][1]) {
                        if (k < K[r][0]) { K[r][3] = K[r][2]; K[r][2] = K[r][1]; K[r][1] = K[r][0]; K[r][0] = k; }
                        else             { K[r][3] = K[r][2]; K[r][2] = K[r][1]; K[r][1] = k; }
                    } else {
                        if (k < K[r][2]) { K[r][3] = K[r][2]; K[r][2] = k; }
                        else             { K[r][3] = k; }
                    }
                }
            }
        }
    }

    // merge across the 8 col lanes (bitonic top-4 of two sorted-4 lists)
    #pragma unroll
    for (int off = 1; off < 8; off <<= 1) {
        #pragma unroll
        for (int r = 0; r < 4; r++) {
            int o0 = __shfl_xor_sync(0xffffffffu, K[r][0], off);
            int o1 = __shfl_xor_sync(0xffffffffu, K[r][1], off);
            int o2 = __shfl_xor_sync(0xffffffffu, K[r][2], off);
            int o3 = __shfl_xor_sync(0xffffffffu, K[r][3], off);
            // stage 1: keep 4 smallest (bitonic split)
            int L0 = min(K[r][0], o3), L1 = min(K[r][1], o2);
            int L2 = min(K[r][2], o1), L3 = min(K[r][3], o0);
            // stage 2+3: sort bitonic 4
            int t0 = min(L0, L2), t2 = max(L0, L2);
            int t1 = min(L1, L3), t3 = max(L1, L3);
            K[r][0] = min(t0, t1); K[r][1] = max(t0, t1);
            K[r][2] = min(t2, t3); K[r][3] = max(t2, t3);
        }
    }
    if ((tid & 7) == 0) {
        #pragma unroll
        for (int r = 0; r < 4; r++) {
            int m = m0 + row4 + r;
            int p = m * GV + g;
            g_top4[p] = make_int4(K[r][0] & 1023, K[r][1] & 1023,
                                  K[r][2] & 1023, K[r][3] & 1023);
            int marg = (K[r][3] >> 10) - (K[r][0] >> 10);
            g_flag[p] = (marg < TAU_HALF) | (int)sclip[row4 + r];
        }
    }
}

// ---------- kernel 3: exact fp32 refine of top-4 (R1-proven arithmetic) ----------
__global__ void k_refine(const float* __restrict__ x, const float* __restrict__ cb,
                         float* __restrict__ out_idx_f) {
    int tid  = threadIdx.x;
    int lane = tid & 31;
    int sub  = lane & 3;
    int p = blockIdx.x * 64 + (tid >> 5) * 8 + (lane >> 2);
    int cand = ((const int*)g_top4)[p * 4 + sub];
    int m = p >> 3, g = p & 7;
    const float* xr = x  + (size_t)m * (GV * DV) + g * DV;
    const float* cr = cb + ((size_t)(g * KV + cand)) * DV;
    float s = 0.f, x2 = 0.f;
    #pragma unroll 8
    for (int k4 = 0; k4 < 32; k4++) {
        float4 xv = *(const float4*)(xr + k4 * 4);
        float4 cv = __ldg((const float4*)(cr + k4 * 4));
        s  = fmaf(xv.x, cv.x, s);  s  = fmaf(xv.y, cv.y, s);
        s  = fmaf(xv.z, cv.z, s);  s  = fmaf(xv.w, cv.w, s);
        x2 = fmaf(xv.x, xv.x, x2); x2 = fmaf(xv.y, xv.y, x2);
        x2 = fmaf(xv.z, xv.z, x2); x2 = fmaf(xv.w, xv.w, x2);
    }
    float d = __fadd_rn(__fsub_rn(x2, __fmul_rn(2.0f, s)), g_c2[g * KV + cand]);
    #pragma unroll
    for (int off = 1; off < 4; off <<= 1) {
        float od = __shfl_xor_sync(0xffffffffu, d, off);
        int   oc = __shfl_xor_sync(0xffffffffu, cand, off);
        if (od < d || (od == d && oc < cand)) { d = od; cand = oc; }
    }
    if (sub == 0) { g_idx[p] = cand; out_idx_f[p] = (float)cand; }
}

// ---------- kernel 4: full exact recheck of flagged tokens (R4-proven) ----------
__global__ void k_fix(const float* __restrict__ x, const float* __restrict__ cb,
                      float* __restrict__ out_idx_f) {
    int warp = threadIdx.x >> 5;
    int lane = threadIdx.x & 31;
    int p = blockIdx.x * 8 + warp;
    if (!g_flag[p]) return;
    int m = p >> 3, g = p & 7;

    const float* xr = x + (size_t)m * (GV * DV) + g * DV;
    float x2 = 0.f;
    #pragma unroll 8
    for (int j = 0; j < 32; j++) {
        float4 v = *(const float4*)(xr + j * 4);
        x2 = fmaf(v.x, v.x, x2); x2 = fmaf(v.y, v.y, x2);
        x2 = fmaf(v.z, v.z, x2); x2 = fmaf(v.w, v.w, x2);
    }
    float best = FLT_MAX; int bi = 0;
    const float* cbg = cb + (size_t)g * KV * DV;
    for (int j = 0; j < 32; j++) {
        int n = lane * 32 + j;
        const float* cr = cbg + (size_t)n * DV;
        float s = 0.f;
        #pragma unroll 8
        for (int k4 = 0; k4 < 32; k4++) {
            float4 xv = *(const float4*)(xr + k4 * 4);
            float4 cv = *(const float4*)(cr + k4 * 4);
            s = fmaf(xv.x, cv.x, s); s = fmaf(xv.y, cv.y, s);
            s = fmaf(xv.z, cv.z, s); s = fmaf(xv.w, cv.w, s);
        }
        float d = __fadd_rn(__fsub_rn(x2, __fmul_rn(2.0f, s)), g_c2[g * KV + n]);
        if (d < best) { best = d; bi = n; }
    }
    #pragma unroll
    for (int off = 16; off > 0; off >>= 1) {
        float ov = __shfl_xor_sync(0xffffffffu, best, off);
        int   oi = __shfl_xor_sync(0xffffffffu, bi,   off);
        if (ov < best || (ov == best && oi < bi)) { best = ov; bi = oi; }
    }
    if (lane == 0) {
        g_idx[p]     = bi;
        out_idx_f[p] = (float)bi;
    }
}

// ---------- kernel 5: gather winners, write quantized, accumulate loss ----------
__global__ void k_quant(const float* __restrict__ x, const float* __restrict__ cb,
                        float* __restrict__ outq) {
    __shared__ float wsums[8];
    int lane = threadIdx.x & 31;
    int w    = threadIdx.x >> 5;
    float acc = 0.f;
    #pragma unroll
    for (int it = 0; it < 8; ++it) {
        int p = blockIdx.x * 64 + w * 8 + it;
        int m = p >> 3, g = p & 7;
        int idx = g_idx[p];
        const float4 xv = *(const float4*)(x  + (size_t)m * (GV*DV) + g * DV + lane * 4);
        const float4 qv = *(const float4*)(cb + ((size_t)g * KV + idx) * DV + lane * 4);
        float4 o;
        o.x = __fadd_rn(xv.x, __fsub_rn(qv.x, xv.x));
        o.y = __fadd_rn(xv.y, __fsub_rn(qv.y, xv.y));
        o.z = __fadd_rn(xv.z, __fsub_rn(qv.z, xv.z));
        o.w = __fadd_rn(xv.w, __fsub_rn(qv.w, xv.w));
        *(float4*)(outq + (size_t)m * (GV*DV) + g * DV + lane * 4) = o;
        float d = __fsub_rn(xv.x, qv.x); float s = d * d;
        d = __fsub_rn(xv.y, qv.y); s = fmaf(d, d, s);
        d = __fsub_rn(xv.z, qv.z); s = fmaf(d, d, s);
        d = __fsub_rn(xv.w, qv.w); s = fmaf(d, d, s);
        #pragma unroll
        for (int o2 = 16; o2 > 0; o2 >>= 1) s += __shfl_xor_sync(0xffffffffu, s, o2);
        if (lane == 0) acc += s;
    }
    if (lane == 0) wsums[w] = acc;
    __syncthreads();
    if (threadIdx.x == 0) {
        double t = 0.0;
        #pragma unroll
        for (int i = 0; i < 8; i++) t += (double)wsums[i];
        atomicAdd(&g_loss, t);
    }
}

// ---------- kernel 6: finalize scalar losses ----------
__global__ void k_fin(float* __restrict__ losses) {
    float L = (float)(g_loss * (1.0 / (double)QN));
    losses[0] = L;
    losses[1] = L;
}

extern "C" void kernel_launch(void* const* d_in, const int* in_sizes, int n_in,
                              void* d_out, int out_size) {
    (void)in_sizes; (void)n_in; (void)out_size;
    const float* x  = (const float*)d_in[0];
    const float* cb = (const float*)d_in[1];
    float* out    = (float*)d_out;
    float* outq   = out;            // [16777216]
    float* losses = out + QN;       // [2]
    float* outidx = out + QN + 2;   // [131072]

    k_prep<<<256, 256>>>(cb);

    cudaFuncSetAttribute(k_main, cudaFuncAttributeMaxDynamicSharedMemorySize, SM_TOTAL);
    k_main<<<dim3(MV / 64, GV), 128, SM_TOTAL>>>(x);

    k_refine<<<NIDX * 4 / 256, 256>>>(x, cb, outidx);
    k_fix<<<NIDX / 8, 256>>>(x, cb, outidx);
    k_quant<<<NIDX / 64, 256>>>(x, cb, outq);
    k_fin<<<1, 1>>>(losses);
}

// round 7
// speedup vs baseline: 1.2822x; 1.2822x over previous
#include <cuda_runtime.h>
#include <cuda_fp16.h>
#include <cfloat>
#include <cstdint>

// Problem constants
#define BV 8
#define TV 2048
#define GV 8
#define KV 1024
#define DV 128
#define MV (BV*TV)            // 16384 tokens
#define QN (MV*GV*DV)         // 16777216 quantized elements
#define NIDX (MV*GV)          // 131072 indices

#define TAU_INT 10486         // 0.08 * 131072, on (key>>10) units
#define VOFF    (1<<20)

// Scratch (static device globals)
__device__ float   g_c2[GV*KV];
__device__ __align__(256) __half2 g_cbh[GV*8*64*128]; // [g][ch][k2][nn]
__device__ int4    g_top4[NIDX];
__device__ int     g_flag[NIDX];
__device__ int     g_idx[NIDX];
__device__ double  g_loss;

// ---------------- helpers ----------------
__device__ __forceinline__ uint32_t smem_to_u32(const void* p) {
    uint32_t a;
    asm("{ .reg .u64 t; cvta.to.shared.u64 t, %1; cvt.u32.u64 %0, t; }" : "=r"(a) : "l"(p));
    return a;
}
__device__ __forceinline__ void cp16(uint32_t dst, const void* src) {
    asm volatile("cp.async.cg.shared.global [%0], [%1], 16;" :: "r"(dst), "l"(src) : "memory");
}
#define CP_COMMIT() asm volatile("cp.async.commit_group;" ::: "memory")
#define CP_WAIT0()  asm volatile("cp.async.wait_group 0;" ::: "memory")

// SMEM layout for k_main (bytes)
#define SM_A    0          // 32768: Ah[k2*128 + m] half2
#define SM_B    32768      // 2 x 32768 double buffer: Bh[k2*128 + nn] half2
#define SM_C2   98304      // 4096
#define SM_TOTAL 102400

// ---------- kernel 1: exact c2 + half2-packed codebook (fragment layout) ----------
__global__ void k_prep(const float* __restrict__ cb) {
    if (blockIdx.x == 0 && threadIdx.x == 0) g_loss = 0.0;
    int warpid = (blockIdx.x * blockDim.x + threadIdx.x) >> 5;   // 0..2047
    int lane = threadIdx.x & 31;
    #pragma unroll
    for (int it = 0; it < 4; ++it) {
        int q = warpid * 4 + it;                                  // (g,n)
        const float4 v = *(const float4*)(cb + (size_t)q * DV + lane * 4);
        float s = v.x * v.x;
        s = fmaf(v.y, v.y, s);
        s = fmaf(v.z, v.z, s);
        s = fmaf(v.w, v.w, s);
        #pragma unroll
        for (int o = 16; o > 0; o >>= 1) s += __shfl_xor_sync(0xffffffffu, s, o);
        if (lane == 0) g_c2[q] = s;
    }
    // pack codebook -> half2: dst ((g*8+ch)*64 + k2)*128 + nn
    int gtid = blockIdx.x * blockDim.x + threadIdx.x;   // 0..65535
    #pragma unroll
    for (int it = 0; it < 8; ++it) {
        int e2 = gtid + it * 65536;          // half2 element 0..524287
        int g   = e2 >> 16;
        int rem = e2 & 65535;
        int n   = rem >> 6;
        int k2  = rem & 63;
        float2 v = *(const float2*)(cb + ((size_t)(g * KV + n)) * DV + 2 * k2);
        g_cbh[((g * 8 + (n >> 7)) * 64 + k2) * 128 + (n & 127)] =
            __floats2half2_rn(v.x, v.y);
    }
}

// ---------- kernel 2: HFMA2 fp16 screen, packed top-4 per token ----------
// CTA: 128 tokens x 1 group; 8 chunks of 128 codes. 256 threads, 8x8 tile.
__global__ void __launch_bounds__(256, 1)
k_main(const float* __restrict__ x) {
    extern __shared__ char smc[];
    __half2* Ah  = (__half2*)(smc + SM_A);
    float*   c2s = (float*)(smc + SM_C2);
    const uint32_t sb = smem_to_u32(smc);

    const int tid   = threadIdx.x;
    const int g     = blockIdx.y;
    const int m0    = blockIdx.x * 128;
    const int row_t = tid >> 4;        // 0..15
    const int col_t = tid & 15;        // 0..15

    // stage A (fp32 -> half2, k2-major)
    #pragma unroll
    for (int i = 0; i < 16; i++) {
        int idx = tid + i * 256;       // 0..4095
        int m  = idx & 127;
        int k4 = idx >> 7;             // 0..31
        float4 v = *(const float4*)(x + (size_t)(m0 + m) * (GV * DV) + g * DV + k4 * 4);
        Ah[(2 * k4)     * 128 + m] = __floats2half2_rn(v.x, v.y);
        Ah[(2 * k4 + 1) * 128 + m] = __floats2half2_rn(v.z, v.w);
    }
    for (int i = tid; i < KV; i += 256) c2s[i] = g_c2[g * KV + i];

    // prefetch B chunk 0 (contiguous 32 KB)
    const char* srcg = (const char*)(g_cbh + (size_t)g * 8 * 64 * 128);
    #pragma unroll
    for (int i = 0; i < 8; i++)
        cp16(sb + SM_B + (tid + i * 256) * 16, srcg + (tid + i * 256) * 16);
    CP_COMMIT();
    __syncthreads();

    int K[8][4];
    #pragma unroll
    for (int r = 0; r < 8; r++)
        #pragma unroll
        for (int j = 0; j < 4; j++) K[r][j] = 0x7FFFFFFF;

    for (int ch = 0; ch < 8; ++ch) {
        CP_WAIT0();
        __syncthreads();   // data ready AND all warps done with prev buffer
        if (ch < 7) {
            uint32_t dst = sb + SM_B + ((ch + 1) & 1) * 32768;
            const char* src = srcg + (size_t)(ch + 1) * 32768;
            #pragma unroll
            for (int i = 0; i < 8; i++)
                cp16(dst + (tid + i * 256) * 16, src + (tid + i * 256) * 16);
            CP_COMMIT();
        }
        const __half2* Bh = (const __half2*)(smc + SM_B + (ch & 1) * 32768);

        __half2 acc[8][8];
        #pragma unroll
        for (int r = 0; r < 8; r++)
            #pragma unroll
            for (int c = 0; c < 8; c++) acc[r][c] = __half2half2(__ushort_as_half(0));

        #pragma unroll 2
        for (int k2 = 0; k2 < 64; ++k2) {
            __half2 a[8], b[8];
            *(int4*)&a[0] = *(const int4*)&Ah[k2 * 128 + row_t * 8];
            *(int4*)&a[4] = *(const int4*)&Ah[k2 * 128 + row_t * 8 + 4];
            *(int4*)&b[0] = *(const int4*)&Bh[k2 * 128 + col_t * 8];
            *(int4*)&b[4] = *(const int4*)&Bh[k2 * 128 + col_t * 8 + 4];
            #pragma unroll
            for (int r = 0; r < 8; r++)
                #pragma unroll
                for (int c = 0; c < 8; c++)
                    acc[r][c] = __hfma2(a[r], b[c], acc[r][c]);
        }

        // epilogue: packed-key top-4 insert (n ascending)
        #pragma unroll
        for (int c = 0; c < 8; c++) {
            int n = ch * 128 + col_t * 8 + c;
            float cf = c2s[n];
            #pragma unroll
            for (int r = 0; r < 8; r++) {
                float2 s2 = __half22float2(acc[r][c]);
                float d = cf - 2.0f * (s2.x + s2.y);
                int v = __float2int_rn(d * 131072.0f) + VOFF;
                int k = (v << 10) | n;
                if (k < K[r][3]) {
                    if (k < K[r][1]) {
                        if (k < K[r][0]) { K[r][3] = K[r][2]; K[r][2] = K[r][1]; K[r][1] = K[r][0]; K[r][0] = k; }
                        else             { K[r][3] = K[r][2]; K[r][2] = K[r][1]; K[r][1] = k; }
                    } else {
                        if (k < K[r][2]) { K[r][3] = K[r][2]; K[r][2] = k; }
                        else             { K[r][3] = k; }
                    }
                }
            }
        }
    }

    // merge top-4 across the 16 col lanes (xor<16 stays within row group)
    #pragma unroll
    for (int off = 1; off < 16; off <<= 1) {
        #pragma unroll
        for (int r = 0; r < 8; r++) {
            int o0 = __shfl_xor_sync(0xffffffffu, K[r][0], off);
            int o1 = __shfl_xor_sync(0xffffffffu, K[r][1], off);
            int o2 = __shfl_xor_sync(0xffffffffu, K[r][2], off);
            int o3 = __shfl_xor_sync(0xffffffffu, K[r][3], off);
            int L0 = min(K[r][0], o3), L1 = min(K[r][1], o2);
            int L2 = min(K[r][2], o1), L3 = min(K[r][3], o0);
            int t0 = min(L0, L2), t2 = max(L0, L2);
            int t1 = min(L1, L3), t3 = max(L1, L3);
            K[r][0] = min(t0, t1); K[r][1] = max(t0, t1);
            K[r][2] = min(t2, t3); K[r][3] = max(t2, t3);
        }
    }
    if (col_t == 0) {
        #pragma unroll
        for (int r = 0; r < 8; r++) {
            int m = m0 + row_t * 8 + r;
            int p = m * GV + g;
            g_top4[p] = make_int4(K[r][0] & 1023, K[r][1] & 1023,
                                  K[r][2] & 1023, K[r][3] & 1023);
            int marg = (K[r][3] >> 10) - (K[r][0] >> 10);
            g_flag[p] = (marg < TAU_INT);
        }
    }
}

// ---------- kernel 3: exact fp32 refine of top-4 (R1-proven arithmetic) ----------
__global__ void k_refine(const float* __restrict__ x, const float* __restrict__ cb,
                         float* __restrict__ out_idx_f) {
    int tid  = threadIdx.x;
    int lane = tid & 31;
    int sub  = lane & 3;
    int p = blockIdx.x * 64 + (tid >> 5) * 8 + (lane >> 2);
    int cand = ((const int*)g_top4)[p * 4 + sub];
    int m = p >> 3, g = p & 7;
    const float* xr = x  + (size_t)m * (GV * DV) + g * DV;
    const float* cr = cb + ((size_t)(g * KV + cand)) * DV;
    float s = 0.f, x2 = 0.f;
    #pragma unroll 8
    for (int k4 = 0; k4 < 32; k4++) {
        float4 xv = *(const float4*)(xr + k4 * 4);
        float4 cv = __ldg((const float4*)(cr + k4 * 4));
        s  = fmaf(xv.x, cv.x, s);  s  = fmaf(xv.y, cv.y, s);
        s  = fmaf(xv.z, cv.z, s);  s  = fmaf(xv.w, cv.w, s);
        x2 = fmaf(xv.x, xv.x, x2); x2 = fmaf(xv.y, xv.y, x2);
        x2 = fmaf(xv.z, xv.z, x2); x2 = fmaf(xv.w, xv.w, x2);
    }
    float d = __fadd_rn(__fsub_rn(x2, __fmul_rn(2.0f, s)), g_c2[g * KV + cand]);
    #pragma unroll
    for (int off = 1; off < 4; off <<= 1) {
        float od = __shfl_xor_sync(0xffffffffu, d, off);
        int   oc = __shfl_xor_sync(0xffffffffu, cand, off);
        if (od < d || (od == d && oc < cand)) { d = od; cand = oc; }
    }
    if (sub == 0) { g_idx[p] = cand; out_idx_f[p] = (float)cand; }
}

// ---------- kernel 4: full exact recheck of flagged tokens (R4-proven) ----------
__global__ void k_fix(const float* __restrict__ x, const float* __restrict__ cb,
                      float* __restrict__ out_idx_f) {
    int warp = threadIdx.x >> 5;
    int lane = threadIdx.x & 31;
    int p = blockIdx.x * 8 + warp;
    if (!g_flag[p]) return;
    int m = p >> 3, g = p & 7;

    const float* xr = x + (size_t)m * (GV * DV) + g * DV;
    float x2 = 0.f;
    #pragma unroll 8
    for (int j = 0; j < 32; j++) {
        float4 v = *(const float4*)(xr + j * 4);
        x2 = fmaf(v.x, v.x, x2); x2 = fmaf(v.y, v.y, x2);
        x2 = fmaf(v.z, v.z, x2); x2 = fmaf(v.w, v.w, x2);
    }
    float best = FLT_MAX; int bi = 0;
    const float* cbg = cb + (size_t)g * KV * DV;
    for (int j = 0; j < 32; j++) {
        int n = lane * 32 + j;
        const float* cr = cbg + (size_t)n * DV;
        float s = 0.f;
        #pragma unroll 8
        for (int k4 = 0; k4 < 32; k4++) {
            float4 xv = *(const float4*)(xr + k4 * 4);
            float4 cv = *(const float4*)(cr + k4 * 4);
            s = fmaf(xv.x, cv.x, s); s = fmaf(xv.y, cv.y, s);
            s = fmaf(xv.z, cv.z, s); s = fmaf(xv.w, cv.w, s);
        }
        float d = __fadd_rn(__fsub_rn(x2, __fmul_rn(2.0f, s)), g_c2[g * KV + n]);
        if (d < best) { best = d; bi = n; }
    }
    #pragma unroll
    for (int off = 16; off > 0; off >>= 1) {
        float ov = __shfl_xor_sync(0xffffffffu, best, off);
        int   oi = __shfl_xor_sync(0xffffffffu, bi,   off);
        if (ov < best || (ov == best && oi < bi)) { best = ov; bi = oi; }
    }
    if (lane == 0) {
        g_idx[p]     = bi;
        out_idx_f[p] = (float)bi;
    }
}

// ---------- kernel 5: gather winners, write quantized, accumulate loss ----------
__global__ void k_quant(const float* __restrict__ x, const float* __restrict__ cb,
                        float* __restrict__ outq) {
    __shared__ float wsums[8];
    int lane = threadIdx.x & 31;
    int w    = threadIdx.x >> 5;
    float acc = 0.f;
    #pragma unroll
    for (int it = 0; it < 8; ++it) {
        int p = blockIdx.x * 64 + w * 8 + it;
        int m = p >> 3, g = p & 7;
        int idx = g_idx[p];
        const float4 xv = *(const float4*)(x  + (size_t)m * (GV*DV) + g * DV + lane * 4);
        const float4 qv = *(const float4*)(cb + ((size_t)g * KV + idx) * DV + lane * 4);
        float4 o;
        o.x = __fadd_rn(xv.x, __fsub_rn(qv.x, xv.x));
        o.y = __fadd_rn(xv.y, __fsub_rn(qv.y, xv.y));
        o.z = __fadd_rn(xv.z, __fsub_rn(qv.z, xv.z));
        o.w = __fadd_rn(xv.w, __fsub_rn(qv.w, xv.w));
        *(float4*)(outq + (size_t)m * (GV*DV) + g * DV + lane * 4) = o;
        float d = __fsub_rn(xv.x, qv.x); float s = d * d;
        d = __fsub_rn(xv.y, qv.y); s = fmaf(d, d, s);
        d = __fsub_rn(xv.z, qv.z); s = fmaf(d, d, s);
        d = __fsub_rn(xv.w, qv.w); s = fmaf(d, d, s);
        #pragma unroll
        for (int o2 = 16; o2 > 0; o2 >>= 1) s += __shfl_xor_sync(0xffffffffu, s, o2);
        if (lane == 0) acc += s;
    }
    if (lane == 0) wsums[w] = acc;
    __syncthreads();
    if (threadIdx.x == 0) {
        double t = 0.0;
        #pragma unroll
        for (int i = 0; i < 8; i++) t += (double)wsums[i];
        atomicAdd(&g_loss, t);
    }
}

// ---------- kernel 6: finalize scalar losses ----------
__global__ void k_fin(float* __restrict__ losses) {
    float L = (float)(g_loss * (1.0 / (double)QN));
    losses[0] = L;
    losses[1] = L;
}

extern "C" void kernel_launch(void* const* d_in, const int* in_sizes, int n_in,
                              void* d_out, int out_size) {
    (void)in_sizes; (void)n_in; (void)out_size;
    const float* x  = (const float*)d_in[0];
    const float* cb = (const float*)d_in[1];
    float* out    = (float*)d_out;
    float* outq   = out;            // [16777216]
    float* losses = out + QN;       // [2]
    float* outidx = out + QN + 2;   // [131072]

    k_prep<<<256, 256>>>(cb);

    cudaFuncSetAttribute(k_main, cudaFuncAttributeMaxDynamicSharedMemorySize, SM_TOTAL);
    k_main<<<dim3(MV / 128, GV), 256, SM_TOTAL>>>(x);

    k_refine<<<NIDX * 4 / 256, 256>>>(x, cb, outidx);
    k_fix<<<NIDX / 8, 256>>>(x, cb, outidx);
    k_quant<<<NIDX / 64, 256>>>(x, cb, outq);
    k_fin<<<1, 1>>>(losses);
}

// round 8
// speedup vs baseline: 4.1959x; 3.2725x over previous
#include <cuda_runtime.h>
#include <cfloat>
#include <cstdint>

// Problem constants
#define BV 8
#define TV 2048
#define GV 8
#define KV 1024
#define DV 128
#define MV (BV*TV)            // 16384 tokens
#define QN (MV*GV*DV)         // 16777216 quantized elements
#define NIDX (MV*GV)          // 131072 indices

// Scratch (static device globals)
__device__ float  g_c2[GV*KV];
__device__ __align__(256) float g_cbT[GV*DV*KV];  // [g][k][n] k-major transposed codebook
__device__ int    g_idx[NIDX];
__device__ double g_loss;
__device__ unsigned int g_cnt;

// ---------- packed fp32x2 helpers ----------
__device__ __forceinline__ void ffma2(unsigned long long& d,
                                      unsigned long long a,
                                      unsigned long long b) {
    asm volatile("fma.rn.f32x2 %0, %1, %2, %0;" : "+l"(d) : "l"(a), "l"(b));
}
__device__ __forceinline__ unsigned long long splat2(float x) {
    unsigned long long r; unsigned u = __float_as_uint(x);
    asm("mov.b64 %0, {%1, %1};" : "=l"(r) : "r"(u));
    return r;
}
__device__ __forceinline__ void unpack2(unsigned long long v, float& lo, float& hi) {
    unsigned a, b;
    asm("mov.b64 {%0, %1}, %2;" : "=r"(a), "=r"(b) : "l"(v));
    lo = __uint_as_float(a); hi = __uint_as_float(b);
}
__device__ __forceinline__ uint32_t smem_to_u32(const void* p) {
    uint32_t a;
    asm("{ .reg .u64 t; cvta.to.shared.u64 t, %1; cvt.u32.u64 %0, t; }" : "=r"(a) : "l"(p));
    return a;
}
__device__ __forceinline__ void cp16(uint32_t dst, const void* src) {
    asm volatile("cp.async.cg.shared.global [%0], [%1], 16;" :: "r"(dst), "l"(src) : "memory");
}
#define CP_COMMIT() asm volatile("cp.async.commit_group;" ::: "memory")
#define CP_WAIT0()  asm volatile("cp.async.wait_group 0;" ::: "memory")

// SMEM layout (bytes)
#define SM_A    0          // 65536: As[k][m] fp32 k-major
#define SM_B    65536      // 2 x 65536: Cs[k][n] fp32 k-major, double buffered
#define SM_X2   196608     // 512
#define SM_MVAL 197120     // 512 (merge)
#define SM_MIDX 197632     // 512
#define SM_TOTAL 198144

// ---------- kernel 1: c2 + k-major codebook transpose + counter reset ----------
__global__ void k_prep(const float* __restrict__ cb) {
    if (blockIdx.x == 0 && threadIdx.x == 0) { g_loss = 0.0; g_cnt = 0u; }
    int warpid = (blockIdx.x * blockDim.x + threadIdx.x) >> 5;   // 0..2047
    int lane = threadIdx.x & 31;
    #pragma unroll
    for (int it = 0; it < 4; ++it) {
        int q = warpid * 4 + it;                                  // (g,n)
        const float4 v = *(const float4*)(cb + (size_t)q * DV + lane * 4);
        float s = v.x * v.x;
        s = fmaf(v.y, v.y, s);
        s = fmaf(v.z, v.z, s);
        s = fmaf(v.w, v.w, s);
        #pragma unroll
        for (int o = 16; o > 0; o >>= 1) s += __shfl_xor_sync(0xffffffffu, s, o);
        if (lane == 0) g_c2[q] = s;
        // transpose this (g,n) row into g_cbT[g][k][n]
        float* dst = g_cbT + (size_t)(q >> 10) * DV * KV + (q & 1023);
        dst[(lane * 4 + 0) * KV] = v.x;
        dst[(lane * 4 + 1) * KV] = v.y;
        dst[(lane * 4 + 2) * KV] = v.z;
        dst[(lane * 4 + 3) * KV] = v.w;
    }
}

// ---------- kernel 2: exact fp32 FFMA2 GEMM + fused argmin ----------
// CTA: 128 tokens x all 1024 codes for one group. 256 threads, 8x8 thread tile.
__global__ void __launch_bounds__(256, 1)
k_main(const float* __restrict__ x, float* __restrict__ out_idx_f) {
    extern __shared__ float sm[];
    float* As  = sm;                          // 16384 floats
    float* x2s = (float*)((char*)sm + SM_X2);
    float* sval = (float*)((char*)sm + SM_MVAL);
    int*   sidx = (int*)((char*)sm + SM_MIDX);
    const uint32_t sb = smem_to_u32(sm);

    const int tid = threadIdx.x;
    const int g   = blockIdx.y;
    const int m0  = blockIdx.x * 128;

    // Load A tile transposed (k-major). lane-over-m => conflict-free STS.
    #pragma unroll
    for (int i = 0; i < 16; i++) {
        int idx = tid + i * 256;          // 0..4095
        int m  = idx & 127;
        int kv = idx >> 7;                // 0..31 (float4 groups along k)
        float4 v = *(const float4*)(x + (size_t)(m0 + m) * (GV * DV) + g * DV + kv * 4);
        float* dst = As + (kv * 4) * 128 + m;
        dst[0]   = v.x;
        dst[128] = v.y;
        dst[256] = v.z;
        dst[384] = v.w;
    }

    // prefetch B chunk 0: Cs[k][n0..n0+127] <- g_cbT[g][k][n0+...]
    const char* srcg = (const char*)(g_cbT + (size_t)g * DV * KV);
    {
        // 4096 x 16B per chunk; thread does 16
        #pragma unroll
        for (int i = 0; i < 16; i++) {
            int u = tid + i * 256;            // 0..4095
            int k  = u >> 5;                  // 0..127
            int n4 = u & 31;                  // 16B unit within 128 cols
            cp16(sb + SM_B + (uint32_t)(k * 512 + n4 * 16),
                 srcg + (size_t)k * 4096 + n4 * 16);
        }
        CP_COMMIT();
    }
    __syncthreads();

    // x2 per row
    if (tid < 128) {
        float s = 0.f;
        #pragma unroll 8
        for (int k = 0; k < 128; k++) { float a = As[k * 128 + tid]; s = fmaf(a, a, s); }
        x2s[tid] = s;
    }
    __syncthreads();

    const int row_t = tid >> 4;           // 0..15 -> rows row_t*8..+7
    const int col_t = tid & 15;           // 0..15 -> cols col_t*8..+7

    float rx2[8];
    #pragma unroll
    for (int i = 0; i < 8; i++) rx2[i] = x2s[row_t * 8 + i];

    float best[8]; int bidx[8];
    #pragma unroll
    for (int i = 0; i < 8; i++) { best[i] = FLT_MAX; bidx[i] = 0; }

    const float* c2g = g_c2 + g * KV;

    for (int n0 = 0; n0 < KV; n0 += 128) {
        CP_WAIT0();
        __syncthreads();     // B chunk ready AND all warps done with the other buffer
        const int ch = n0 >> 7;
        if (n0 + 128 < KV) {
            uint32_t dst = sb + SM_B + (uint32_t)(((ch + 1) & 1) * 65536);
            const char* src = srcg + (size_t)(n0 + 128) * 4;
            #pragma unroll
            for (int i = 0; i < 16; i++) {
                int u = tid + i * 256;
                int k  = u >> 5;
                int n4 = u & 31;
                cp16(dst + (uint32_t)(k * 512 + n4 * 16),
                     src + (size_t)k * 4096 + n4 * 16);
            }
            CP_COMMIT();
        }
        const float* Cs = sm + 16384 + (ch & 1) * 16384;

        // 8x8 thread tile, rows packed in pairs for f32x2
        unsigned long long acc[4][8];
        #pragma unroll
        for (int p = 0; p < 4; p++)
            #pragma unroll
            for (int j = 0; j < 8; j++) acc[p][j] = 0ULL;

        #pragma unroll 8
        for (int k = 0; k < 128; k++) {
            const float* ar = As + k * 128 + row_t * 8;
            ulonglong2 a01 = *(const ulonglong2*)ar;        // rows (0,1),(2,3)
            ulonglong2 a23 = *(const ulonglong2*)(ar + 4);  // rows (4,5),(6,7)
            const float* cr = Cs + k * 128 + col_t * 8;
            float4 c0 = *(const float4*)cr;
            float4 c1 = *(const float4*)(cr + 4);
            unsigned long long cj[8];
            cj[0] = splat2(c0.x); cj[1] = splat2(c0.y);
            cj[2] = splat2(c0.z); cj[3] = splat2(c0.w);
            cj[4] = splat2(c1.x); cj[5] = splat2(c1.y);
            cj[6] = splat2(c1.z); cj[7] = splat2(c1.w);
            #pragma unroll
            for (int j = 0; j < 8; j++) {
                ffma2(acc[0][j], a01.x, cj[j]);
                ffma2(acc[1][j], a01.y, cj[j]);
                ffma2(acc[2][j], a23.x, cj[j]);
                ffma2(acc[3][j], a23.y, cj[j]);
            }
        }

        // Epilogue: dist = (x2 - 2*xc) + c2, mirroring reference rounding.
        #pragma unroll
        for (int j = 0; j < 8; j++) {
            int n = n0 + col_t * 8 + j;
            float cc = __ldg(c2g + n);
            #pragma unroll
            for (int p = 0; p < 4; p++) {
                float lo, hi; unpack2(acc[p][j], lo, hi);
                float d0 = __fadd_rn(__fsub_rn(rx2[2*p],   __fmul_rn(2.0f, lo)), cc);
                float d1 = __fadd_rn(__fsub_rn(rx2[2*p+1], __fmul_rn(2.0f, hi)), cc);
                if (d0 < best[2*p])   { best[2*p]   = d0; bidx[2*p]   = n; }
                if (d1 < best[2*p+1]) { best[2*p+1] = d1; bidx[2*p+1] = n; }
            }
        }
    }

    // Merge across 16 col-lanes (same row_t group stays within xor<16)
    #pragma unroll
    for (int off = 1; off < 16; off <<= 1) {
        #pragma unroll
        for (int i = 0; i < 8; i++) {
            float ov = __shfl_xor_sync(0xffffffffu, best[i], off);
            int   oi = __shfl_xor_sync(0xffffffffu, bidx[i], off);
            if (ov < best[i] || (ov == best[i] && oi < bidx[i])) {
                best[i] = ov; bidx[i] = oi;
            }
        }
    }
    if (col_t == 0) {
        #pragma unroll
        for (int i = 0; i < 8; i++) {
            int m = m0 + row_t * 8 + i;
            g_idx[m * GV + g]     = bidx[i];
            out_idx_f[m * GV + g] = (float)bidx[i];
        }
    }
    (void)sval; (void)sidx;
}

// ---------- kernel 3: gather winners, write quantized, accumulate loss, finalize ----------
__global__ void k_quant(const float* __restrict__ x, const float* __restrict__ cb,
                        float* __restrict__ outq, float* __restrict__ losses) {
    __shared__ float wsums[8];
    int lane = threadIdx.x & 31;
    int w    = threadIdx.x >> 5;
    float acc = 0.f;
    #pragma unroll
    for (int it = 0; it < 8; ++it) {
        int p = blockIdx.x * 64 + w * 8 + it;   // (m,g) pair
        int m = p >> 3, g = p & 7;
        int idx = g_idx[p];
        const float4 xv = *(const float4*)(x  + (size_t)m * (GV*DV) + g * DV + lane * 4);
        const float4 qv = *(const float4*)(cb + ((size_t)g * KV + idx) * DV + lane * 4);
        // quantized = xs + (q - xs), exactly as the reference computes it
        float4 o;
        o.x = __fadd_rn(xv.x, __fsub_rn(qv.x, xv.x));
        o.y = __fadd_rn(xv.y, __fsub_rn(qv.y, xv.y));
        o.z = __fadd_rn(xv.z, __fsub_rn(qv.z, xv.z));
        o.w = __fadd_rn(xv.w, __fsub_rn(qv.w, xv.w));
        *(float4*)(outq + (size_t)m * (GV*DV) + g * DV + lane * 4) = o;
        float d = __fsub_rn(xv.x, qv.x); float s = d * d;
        d = __fsub_rn(xv.y, qv.y); s = fmaf(d, d, s);
        d = __fsub_rn(xv.z, qv.z); s = fmaf(d, d, s);
        d = __fsub_rn(xv.w, qv.w); s = fmaf(d, d, s);
        #pragma unroll
        for (int o2 = 16; o2 > 0; o2 >>= 1) s += __shfl_xor_sync(0xffffffffu, s, o2);
        if (lane == 0) acc += s;
    }
    if (lane == 0) wsums[w] = acc;
    __syncthreads();
    if (threadIdx.x == 0) {
        double t = 0.0;
        #pragma unroll
        for (int i = 0; i < 8; i++) t += (double)wsums[i];
        atomicAdd(&g_loss, t);
        __threadfence();
        unsigned int done = atomicAdd(&g_cnt, 1u);
        if (done == gridDim.x - 1) {
            float L = (float)(g_loss * (1.0 / (double)QN));
            losses[0] = L;   // commitment_loss
            losses[1] = L;   // codebook_loss (identical value)
        }
    }
}

extern "C" void kernel_launch(void* const* d_in, const int* in_sizes, int n_in,
                              void* d_out, int out_size) {
    (void)in_sizes; (void)n_in; (void)out_size;
    const float* x  = (const float*)d_in[0];
    const float* cb = (const float*)d_in[1];
    float* out    = (float*)d_out;
    float* outq   = out;            // [16777216]
    float* losses = out + QN;       // [2]
    float* outidx = out + QN + 2;   // [131072]

    k_prep<<<256, 256>>>(cb);

    cudaFuncSetAttribute(k_main, cudaFuncAttributeMaxDynamicSharedMemorySize, SM_TOTAL);
    k_main<<<dim3(MV / 128, GV), 256, SM_TOTAL>>>(x, outidx);

    k_quant<<<NIDX / 64, 256>>>(x, cb, outq, losses);
}

// round 10
// speedup vs baseline: 4.2123x; 1.0039x over previous
#include <cuda_runtime.h>
#include <cfloat>
#include <cstdint>

// Problem constants
#define BV 8
#define TV 2048
#define GV 8
#define KV 1024
#define DV 128
#define MV (BV*TV)            // 16384 tokens
#define QN (MV*GV*DV)         // 16777216 quantized elements
#define NIDX (MV*GV)          // 131072 indices

// Scratch (static device globals)
__device__ float  g_c2[GV*KV];
__device__ __align__(256) float g_cbT[GV*DV*KV];  // [g][k][n] k-major transposed codebook
__device__ double g_loss;
__device__ unsigned int g_cnt;

// ---------- packed fp32x2 helpers ----------
__device__ __forceinline__ void ffma2(unsigned long long& d,
                                      unsigned long long a,
                                      unsigned long long b) {
    asm volatile("fma.rn.f32x2 %0, %1, %2, %0;" : "+l"(d) : "l"(a), "l"(b));
}
__device__ __forceinline__ unsigned long long splat2(float x) {
    unsigned long long r; unsigned u = __float_as_uint(x);
    asm("mov.b64 %0, {%1, %1};" : "=l"(r) : "r"(u));
    return r;
}
__device__ __forceinline__ void unpack2(unsigned long long v, float& lo, float& hi) {
    unsigned a, b;
    asm("mov.b64 {%0, %1}, %2;" : "=r"(a), "=r"(b) : "l"(v));
    lo = __uint_as_float(a); hi = __uint_as_float(b);
}
__device__ __forceinline__ uint32_t smem_to_u32(const void* p) {
    uint32_t a;
    asm("{ .reg .u64 t; cvta.to.shared.u64 t, %1; cvt.u32.u64 %0, t; }" : "=r"(a) : "l"(p));
    return a;
}
__device__ __forceinline__ void cp16(uint32_t dst, const void* src) {
    asm volatile("cp.async.cg.shared.global [%0], [%1], 16;" :: "r"(dst), "l"(src) : "memory");
}
#define CP_COMMIT() asm volatile("cp.async.commit_group;" ::: "memory")
#define CP_WAIT0()  asm volatile("cp.async.wait_group 0;" ::: "memory")

// SMEM layout (bytes) for k_main
#define SM_A    0          // 65536: As[k][m] fp32 k-major
#define SM_B    65536      // 2 x 65536: Cs[k][n] fp32 k-major, double buffered
#define SM_X2   196608     // 512
#define SM_MIDX 197120     // 512 (winning index broadcast)
#define SM_WSUM 197632     // 32  (loss partials)
#define SM_TOTAL 197664

// ---------- kernel 1: c2 + coalesced k-major transpose + counter reset ----------
// One block per (g, 32-code tile): grid 8*32=256 blocks, 256 threads.
__global__ void k_prep(const float* __restrict__ cb) {
    __shared__ float tile[32 * 129];   // [code][k], pad 129 for conflict-free transpose
    if (blockIdx.x == 0 && threadIdx.x == 0) { g_loss = 0.0; g_cnt = 0u; }

    const int tid = threadIdx.x;
    const int g   = blockIdx.x >> 5;          // 0..7
    const int n0  = (blockIdx.x & 31) * 32;   // code tile base

    // load 32 codes x 128 dims (coalesced)
    const float* src = cb + ((size_t)g * KV + n0) * DV;
    #pragma unroll
    for (int i = 0; i < 4; i++) {
        int u = tid + i * 256;                 // float4 unit 0..1023
        int n  = u >> 5;                       // code 0..31
        int k4 = u & 31;
        float4 v = *(const float4*)(src + (size_t)n * DV + k4 * 4);
        float* d = &tile[n * 129 + k4 * 4];
        d[0] = v.x; d[1] = v.y; d[2] = v.z; d[3] = v.w;
    }
    __syncthreads();

    // c2 for 32 codes: warp w handles codes 4w..4w+3 (8 warps x 4).
    // NOTE: scalar loads — tile rows are 129 floats, so odd rows are NOT
    // 16B-aligned; a float4 load here traps (R9 bug).
    {
        int lane = tid & 31, w = tid >> 5;
        #pragma unroll
        for (int it = 0; it < 4; ++it) {
            int n = w * 4 + it;
            const float* row = &tile[n * 129 + lane * 4];
            float a0 = row[0], a1 = row[1], a2 = row[2], a3 = row[3];
            float s = a0 * a0;
            s = fmaf(a1, a1, s);
            s = fmaf(a2, a2, s);
            s = fmaf(a3, a3, s);
            #pragma unroll
            for (int o = 16; o > 0; o >>= 1) s += __shfl_xor_sync(0xffffffffu, s, o);
            if (lane == 0) g_c2[g * KV + n0 + n] = s;
        }
    }

    // transposed write: g_cbT[g][k][n0+n], 32 consecutive n per k -> coalesced
    float* dstg = g_cbT + (size_t)g * DV * KV + n0;
    #pragma unroll
    for (int i = 0; i < 16; i++) {
        int u = tid + i * 256;                 // 0..4095
        int k = u >> 5;                        // 0..127
        int n = u & 31;
        dstg[(size_t)k * KV + n] = tile[n * 129 + k];
    }
}

// ---------- kernel 2: exact fp32 FFMA2 GEMM + argmin + fused quantize/loss ----------
// CTA: 128 tokens x all 1024 codes for one group. 256 threads, 8x8 thread tile.
__global__ void __launch_bounds__(256, 1)
k_main(const float* __restrict__ x, const float* __restrict__ cb,
       float* __restrict__ outq, float* __restrict__ losses,
       float* __restrict__ out_idx_f) {
    extern __shared__ float sm[];
    float* As   = sm;                          // 16384 floats
    float* x2s  = (float*)((char*)sm + SM_X2);
    int*   sidx = (int*)((char*)sm + SM_MIDX);
    float* wsum = (float*)((char*)sm + SM_WSUM);
    const uint32_t sb = smem_to_u32(sm);

    const int tid = threadIdx.x;
    const int g   = blockIdx.y;
    const int m0  = blockIdx.x * 128;

    // Load A tile transposed (k-major). lane-over-m => conflict-free STS.
    #pragma unroll
    for (int i = 0; i < 16; i++) {
        int idx = tid + i * 256;          // 0..4095
        int m  = idx & 127;
        int kv = idx >> 7;                // 0..31 (float4 groups along k)
        float4 v = *(const float4*)(x + (size_t)(m0 + m) * (GV * DV) + g * DV + kv * 4);
        float* dst = As + (kv * 4) * 128 + m;
        dst[0]   = v.x;
        dst[128] = v.y;
        dst[256] = v.z;
        dst[384] = v.w;
    }

    // prefetch B chunk 0: Cs[k][n0..n0+127] <- g_cbT[g][k][...]
    const char* srcg = (const char*)(g_cbT + (size_t)g * DV * KV);
    {
        #pragma unroll
        for (int i = 0; i < 16; i++) {
            int u = tid + i * 256;            // 0..4095
            int k  = u >> 5;                  // 0..127
            int n4 = u & 31;                  // 16B unit within 128 cols
            cp16(sb + SM_B + (uint32_t)(k * 512 + n4 * 16),
                 srcg + (size_t)k * 4096 + n4 * 16);
        }
        CP_COMMIT();
    }
    __syncthreads();

    // x2 per row
    if (tid < 128) {
        float s = 0.f;
        #pragma unroll 8
        for (int k = 0; k < 128; k++) { float a = As[k * 128 + tid]; s = fmaf(a, a, s); }
        x2s[tid] = s;
    }
    __syncthreads();

    const int row_t = tid >> 4;           // 0..15 -> rows row_t*8..+7
    const int col_t = tid & 15;           // 0..15 -> cols col_t*8..+7

    float rx2[8];
    #pragma unroll
    for (int i = 0; i < 8; i++) rx2[i] = x2s[row_t * 8 + i];

    float best[8]; int bidx[8];
    #pragma unroll
    for (int i = 0; i < 8; i++) { best[i] = FLT_MAX; bidx[i] = 0; }

    const float* c2g = g_c2 + g * KV;

    for (int n0 = 0; n0 < KV; n0 += 128) {
        CP_WAIT0();
        __syncthreads();     // B chunk ready AND all warps done with the other buffer
        const int ch = n0 >> 7;
        if (n0 + 128 < KV) {
            uint32_t dst = sb + SM_B + (uint32_t)(((ch + 1) & 1) * 65536);
            const char* src = srcg + (size_t)(n0 + 128) * 4;
            #pragma unroll
            for (int i = 0; i < 16; i++) {
                int u = tid + i * 256;
                int k  = u >> 5;
                int n4 = u & 31;
                cp16(dst + (uint32_t)(k * 512 + n4 * 16),
                     src + (size_t)k * 4096 + n4 * 16);
            }
            CP_COMMIT();
        }
        const float* Cs = sm + 16384 + (ch & 1) * 16384;

        // 8x8 thread tile, rows packed in pairs for f32x2
        unsigned long long acc[4][8];
        #pragma unroll
        for (int p = 0; p < 4; p++)
            #pragma unroll
            for (int j = 0; j < 8; j++) acc[p][j] = 0ULL;

        #pragma unroll 8
        for (int k = 0; k < 128; k++) {
            const float* ar = As + k * 128 + row_t * 8;
            ulonglong2 a01 = *(const ulonglong2*)ar;        // rows (0,1),(2,3)
            ulonglong2 a23 = *(const ulonglong2*)(ar + 4);  // rows (4,5),(6,7)
            const float* cr = Cs + k * 128 + col_t * 8;
            float4 c0 = *(const float4*)cr;
            float4 c1 = *(const float4*)(cr + 4);
            unsigned long long cj[8];
            cj[0] = splat2(c0.x); cj[1] = splat2(c0.y);
            cj[2] = splat2(c0.z); cj[3] = splat2(c0.w);
            cj[4] = splat2(c1.x); cj[5] = splat2(c1.y);
            cj[6] = splat2(c1.z); cj[7] = splat2(c1.w);
            #pragma unroll
            for (int j = 0; j < 8; j++) {
                ffma2(acc[0][j], a01.x, cj[j]);
                ffma2(acc[1][j], a01.y, cj[j]);
                ffma2(acc[2][j], a23.x, cj[j]);
                ffma2(acc[3][j], a23.y, cj[j]);
            }
        }

        // Epilogue: dist = (x2 - 2*xc) + c2, mirroring reference rounding.
        #pragma unroll
        for (int j = 0; j < 8; j++) {
            int n = n0 + col_t * 8 + j;
            float cc = __ldg(c2g + n);
            #pragma unroll
            for (int p = 0; p < 4; p++) {
                float lo, hi; unpack2(acc[p][j], lo, hi);
                float d0 = __fadd_rn(__fsub_rn(rx2[2*p],   __fmul_rn(2.0f, lo)), cc);
                float d1 = __fadd_rn(__fsub_rn(rx2[2*p+1], __fmul_rn(2.0f, hi)), cc);
                if (d0 < best[2*p])   { best[2*p]   = d0; bidx[2*p]   = n; }
                if (d1 < best[2*p+1]) { best[2*p+1] = d1; bidx[2*p+1] = n; }
            }
        }
    }

    // Merge across 16 col-lanes (same row_t group stays within xor<16)
    #pragma unroll
    for (int off = 1; off < 16; off <<= 1) {
        #pragma unroll
        for (int i = 0; i < 8; i++) {
            float ov = __shfl_xor_sync(0xffffffffu, best[i], off);
            int   oi = __shfl_xor_sync(0xffffffffu, bidx[i], off);
            if (ov < best[i] || (ov == best[i] && oi < bidx[i])) {
                best[i] = ov; bidx[i] = oi;
            }
        }
    }
    if (col_t == 0) {
        #pragma unroll
        for (int i = 0; i < 8; i++) {
            int m = m0 + row_t * 8 + i;
            sidx[row_t * 8 + i]   = bidx[i];
            out_idx_f[m * GV + g] = (float)bidx[i];
        }
    }
    __syncthreads();

    // ---- fused quantize + loss for this CTA's 128 tokens x this group ----
    const float* cbg = cb + (size_t)g * KV * DV;
    float lacc = 0.f;
    #pragma unroll
    for (int i = 0; i < 16; i++) {
        int u = tid + i * 256;            // 0..4095
        int m  = u >> 5;                  // token 0..127 (same m across a warp)
        int k4 = u & 31;
        int idx = sidx[m];
        const float4 xv = *(const float4*)(x + (size_t)(m0 + m) * (GV * DV) + g * DV + k4 * 4);
        const float4 qv = __ldg((const float4*)(cbg + (size_t)idx * DV + k4 * 4));
        // quantized = xs + (q - xs), exactly as the reference computes it
        float4 o;
        o.x = __fadd_rn(xv.x, __fsub_rn(qv.x, xv.x));
        o.y = __fadd_rn(xv.y, __fsub_rn(qv.y, xv.y));
        o.z = __fadd_rn(xv.z, __fsub_rn(qv.z, xv.z));
        o.w = __fadd_rn(xv.w, __fsub_rn(qv.w, xv.w));
        *(float4*)(outq + (size_t)(m0 + m) * (GV * DV) + g * DV + k4 * 4) = o;
        float d = __fsub_rn(xv.x, qv.x); lacc = fmaf(d, d, lacc);
        d = __fsub_rn(xv.y, qv.y); lacc = fmaf(d, d, lacc);
        d = __fsub_rn(xv.z, qv.z); lacc = fmaf(d, d, lacc);
        d = __fsub_rn(xv.w, qv.w); lacc = fmaf(d, d, lacc);
    }
    #pragma unroll
    for (int o = 16; o > 0; o >>= 1) lacc += __shfl_xor_sync(0xffffffffu, lacc, o);
    if ((tid & 31) == 0) wsum[tid >> 5] = lacc;
    __syncthreads();
    if (tid == 0) {
        double t = 0.0;
        #pragma unroll
        for (int i = 0; i < 8; i++) t += (double)wsum[i];
        atomicAdd(&g_loss, t);
        __threadfence();
        unsigned int done = atomicAdd(&g_cnt, 1u);
        if (done == (unsigned int)(gridDim.x * gridDim.y) - 1u) {
            float L = (float)(g_loss * (1.0 / (double)QN));
            losses[0] = L;   // commitment_loss
            losses[1] = L;   // codebook_loss (identical value)
        }
    }
}

extern "C" void kernel_launch(void* const* d_in, const int* in_sizes, int n_in,
                              void* d_out, int out_size) {
    (void)in_sizes; (void)n_in; (void)out_size;
    const float* x  = (const float*)d_in[0];
    const float* cb = (const float*)d_in[1];
    float* out    = (float*)d_out;
    float* outq   = out;            // [16777216]
    float* losses = out + QN;       // [2]
    float* outidx = out + QN + 2;   // [131072]

    k_prep<<<256, 256>>>(cb);

    cudaFuncSetAttribute(k_main, cudaFuncAttributeMaxDynamicSharedMemorySize, SM_TOTAL);
    k_main<<<dim3(MV / 128, GV), 256, SM_TOTAL>>>(x, cb, outq, losses, outidx);
}

// round 11
// speedup vs baseline: 4.2170x; 1.0011x over previous
#include <cuda_runtime.h>
#include <cfloat>
#include <cstdint>

// Problem constants
#define BV 8
#define TV 2048
#define GV 8
#define KV 1024
#define DV 128
#define MV (BV*TV)            // 16384 tokens
#define QN (MV*GV*DV)         // 16777216 quantized elements
#define NIDX (MV*GV)          // 131072 indices

// Scratch (static device globals)
__device__ float  g_c2[GV*KV];
__device__ __align__(256) float g_cbT[GV*DV*KV];  // [g][k][n] k-major transposed codebook
__device__ double g_loss;
__device__ unsigned int g_cnt;

// ---------- packed fp32x2 helpers ----------
__device__ __forceinline__ void ffma2(unsigned long long& d,
                                      unsigned long long a,
                                      unsigned long long b) {
    asm volatile("fma.rn.f32x2 %0, %1, %2, %0;" : "+l"(d) : "l"(a), "l"(b));
}
__device__ __forceinline__ unsigned long long splat2(float x) {
    unsigned long long r; unsigned u = __float_as_uint(x);
    asm("mov.b64 %0, {%1, %1};" : "=l"(r) : "r"(u));
    return r;
}
__device__ __forceinline__ void unpack2(unsigned long long v, float& lo, float& hi) {
    unsigned a, b;
    asm("mov.b64 {%0, %1}, %2;" : "=r"(a), "=r"(b) : "l"(v));
    lo = __uint_as_float(a); hi = __uint_as_float(b);
}
__device__ __forceinline__ uint32_t smem_to_u32(const void* p) {
    uint32_t a;
    asm("{ .reg .u64 t; cvta.to.shared.u64 t, %1; cvt.u32.u64 %0, t; }" : "=r"(a) : "l"(p));
    return a;
}
__device__ __forceinline__ void cp16(uint32_t dst, const void* src) {
    asm volatile("cp.async.cg.shared.global [%0], [%1], 16;" :: "r"(dst), "l"(src) : "memory");
}
#define CP_COMMIT() asm volatile("cp.async.commit_group;" ::: "memory")
#define CP_WAIT0()  asm volatile("cp.async.wait_group 0;" ::: "memory")

// SMEM layout (bytes) for k_main
#define SM_A    0          // 65536: As[k][m] fp32 k-major
#define SM_B    65536      // 2 x 65536: Cs[k][n] fp32 k-major, double buffered
#define SM_X2   196608     // 512
#define SM_MIDX 197120     // 512 (winning index broadcast)
#define SM_WSUM 197632     // 32  (loss partials)
#define SM_TOTAL 197664

// ---------- kernel 1: c2 + coalesced k-major transpose + counter reset ----------
// One block per (g, 32-code tile): grid 8*32=256 blocks, 256 threads.
__global__ void k_prep(const float* __restrict__ cb) {
    __shared__ float tile[32 * 129];   // [code][k], pad 129 for conflict-free transpose
    if (blockIdx.x == 0 && threadIdx.x == 0) { g_loss = 0.0; g_cnt = 0u; }

    const int tid = threadIdx.x;
    const int g   = blockIdx.x >> 5;          // 0..7
    const int n0  = (blockIdx.x & 31) * 32;   // code tile base

    // load 32 codes x 128 dims (coalesced)
    const float* src = cb + ((size_t)g * KV + n0) * DV;
    #pragma unroll
    for (int i = 0; i < 4; i++) {
        int u = tid + i * 256;                 // float4 unit 0..1023
        int n  = u >> 5;                       // code 0..31
        int k4 = u & 31;
        float4 v = *(const float4*)(src + (size_t)n * DV + k4 * 4);
        float* d = &tile[n * 129 + k4 * 4];
        d[0] = v.x; d[1] = v.y; d[2] = v.z; d[3] = v.w;
    }
    __syncthreads();

    // c2 for 32 codes: warp w handles codes 4w..4w+3 (8 warps x 4).
    // NOTE: scalar loads — tile rows are 129 floats, so odd rows are NOT
    // 16B-aligned; a float4 load here traps (R9 bug).
    {
        int lane = tid & 31, w = tid >> 5;
        #pragma unroll
        for (int it = 0; it < 4; ++it) {
            int n = w * 4 + it;
            const float* row = &tile[n * 129 + lane * 4];
            float a0 = row[0], a1 = row[1], a2 = row[2], a3 = row[3];
            float s = a0 * a0;
            s = fmaf(a1, a1, s);
            s = fmaf(a2, a2, s);
            s = fmaf(a3, a3, s);
            #pragma unroll
            for (int o = 16; o > 0; o >>= 1) s += __shfl_xor_sync(0xffffffffu, s, o);
            if (lane == 0) g_c2[g * KV + n0 + n] = s;
        }
    }

    // transposed write: g_cbT[g][k][n0+n], 32 consecutive n per k -> coalesced
    float* dstg = g_cbT + (size_t)g * DV * KV + n0;
    #pragma unroll
    for (int i = 0; i < 16; i++) {
        int u = tid + i * 256;                 // 0..4095
        int k = u >> 5;                        // 0..127
        int n = u & 31;
        dstg[(size_t)k * KV + n] = tile[n * 129 + k];
    }
}

// ---------- kernel 2: exact fp32 FFMA2 GEMM + argmin + fused quantize/loss ----------
// CTA: 128 tokens x all 1024 codes for one group. 256 threads, 8x8 thread tile.
__global__ void __launch_bounds__(256, 1)
k_main(const float* __restrict__ x, const float* __restrict__ cb,
       float* __restrict__ outq, float* __restrict__ losses,
       float* __restrict__ out_idx_f) {
    extern __shared__ float sm[];
    float* As   = sm;                          // 16384 floats
    float* x2s  = (float*)((char*)sm + SM_X2);
    int*   sidx = (int*)((char*)sm + SM_MIDX);
    float* wsum = (float*)((char*)sm + SM_WSUM);
    const uint32_t sb = smem_to_u32(sm);

    const int tid = threadIdx.x;
    const int g   = blockIdx.y;
    const int m0  = blockIdx.x * 128;

    // Load A tile transposed (k-major). lane-over-m => conflict-free STS.
    #pragma unroll
    for (int i = 0; i < 16; i++) {
        int idx = tid + i * 256;          // 0..4095
        int m  = idx & 127;
        int kv = idx >> 7;                // 0..31 (float4 groups along k)
        float4 v = *(const float4*)(x + (size_t)(m0 + m) * (GV * DV) + g * DV + kv * 4);
        float* dst = As + (kv * 4) * 128 + m;
        dst[0]   = v.x;
        dst[128] = v.y;
        dst[256] = v.z;
        dst[384] = v.w;
    }

    // prefetch B chunk 0: Cs[k][n0..n0+127] <- g_cbT[g][k][...]
    const char* srcg = (const char*)(g_cbT + (size_t)g * DV * KV);
    {
        #pragma unroll
        for (int i = 0; i < 16; i++) {
            int u = tid + i * 256;            // 0..4095
            int k  = u >> 5;                  // 0..127
            int n4 = u & 31;                  // 16B unit within 128 cols
            cp16(sb + SM_B + (uint32_t)(k * 512 + n4 * 16),
                 srcg + (size_t)k * 4096 + n4 * 16);
        }
        CP_COMMIT();
    }
    __syncthreads();

    // x2 per row
    if (tid < 128) {
        float s = 0.f;
        #pragma unroll 8
        for (int k = 0; k < 128; k++) { float a = As[k * 128 + tid]; s = fmaf(a, a, s); }
        x2s[tid] = s;
    }
    __syncthreads();

    const int row_t = tid >> 4;           // 0..15 -> rows row_t*8..+7
    const int col_t = tid & 15;           // 0..15 -> cols col_t*8..+7

    float rx2[8];
    #pragma unroll
    for (int i = 0; i < 8; i++) rx2[i] = x2s[row_t * 8 + i];

    float best[8]; int bidx[8];
    #pragma unroll
    for (int i = 0; i < 8; i++) { best[i] = FLT_MAX; bidx[i] = 0; }

    const float* c2g = g_c2 + g * KV;

    for (int n0 = 0; n0 < KV; n0 += 128) {
        CP_WAIT0();
        __syncthreads();     // B chunk ready AND all warps done with the other buffer
        const int ch = n0 >> 7;
        if (n0 + 128 < KV) {
            uint32_t dst = sb + SM_B + (uint32_t)(((ch + 1) & 1) * 65536);
            const char* src = srcg + (size_t)(n0 + 128) * 4;
            #pragma unroll
            for (int i = 0; i < 16; i++) {
                int u = tid + i * 256;
                int k  = u >> 5;
                int n4 = u & 31;
                cp16(dst + (uint32_t)(k * 512 + n4 * 16),
                     src + (size_t)k * 4096 + n4 * 16);
            }
            CP_COMMIT();
        }
        const float* Cs = sm + 16384 + (ch & 1) * 16384;

        // 8x8 thread tile, rows packed in pairs for f32x2
        unsigned long long acc[4][8];
        #pragma unroll
        for (int p = 0; p < 4; p++)
            #pragma unroll
            for (int j = 0; j < 8; j++) acc[p][j] = 0ULL;

        #pragma unroll 8
        for (int k = 0; k < 128; k++) {
            const float* ar = As + k * 128 + row_t * 8;
            ulonglong2 a01 = *(const ulonglong2*)ar;        // rows (0,1),(2,3)
            ulonglong2 a23 = *(const ulonglong2*)(ar + 4);  // rows (4,5),(6,7)
            const float* cr = Cs + k * 128 + col_t * 8;
            float4 c0 = *(const float4*)cr;
            float4 c1 = *(const float4*)(cr + 4);
            unsigned long long cj[8];
            cj[0] = splat2(c0.x); cj[1] = splat2(c0.y);
            cj[2] = splat2(c0.z); cj[3] = splat2(c0.w);
            cj[4] = splat2(c1.x); cj[5] = splat2(c1.y);
            cj[6] = splat2(c1.z); cj[7] = splat2(c1.w);
            #pragma unroll
            for (int j = 0; j < 8; j++) {
                ffma2(acc[0][j], a01.x, cj[j]);
                ffma2(acc[1][j], a01.y, cj[j]);
                ffma2(acc[2][j], a23.x, cj[j]);
                ffma2(acc[3][j], a23.y, cj[j]);
            }
        }

        // Epilogue: dist = (x2 - 2*xc) + c2, mirroring reference rounding.
        #pragma unroll
        for (int j = 0; j < 8; j++) {
            int n = n0 + col_t * 8 + j;
            float cc = __ldg(c2g + n);
            #pragma unroll
            for (int p = 0; p < 4; p++) {
                float lo, hi; unpack2(acc[p][j], lo, hi);
                float d0 = __fadd_rn(__fsub_rn(rx2[2*p],   __fmul_rn(2.0f, lo)), cc);
                float d1 = __fadd_rn(__fsub_rn(rx2[2*p+1], __fmul_rn(2.0f, hi)), cc);
                if (d0 < best[2*p])   { best[2*p]   = d0; bidx[2*p]   = n; }
                if (d1 < best[2*p+1]) { best[2*p+1] = d1; bidx[2*p+1] = n; }
            }
        }
    }

    // Merge across 16 col-lanes (same row_t group stays within xor<16)
    #pragma unroll
    for (int off = 1; off < 16; off <<= 1) {
        #pragma unroll
        for (int i = 0; i < 8; i++) {
            float ov = __shfl_xor_sync(0xffffffffu, best[i], off);
            int   oi = __shfl_xor_sync(0xffffffffu, bidx[i], off);
            if (ov < best[i] || (ov == best[i] && oi < bidx[i])) {
                best[i] = ov; bidx[i] = oi;
            }
        }
    }
    if (col_t == 0) {
        #pragma unroll
        for (int i = 0; i < 8; i++) {
            int m = m0 + row_t * 8 + i;
            sidx[row_t * 8 + i]   = bidx[i];
            out_idx_f[m * GV + g] = (float)bidx[i];
        }
    }
    __syncthreads();

    // ---- fused quantize + loss for this CTA's 128 tokens x this group ----
    const float* cbg = cb + (size_t)g * KV * DV;
    float lacc = 0.f;
    #pragma unroll
    for (int i = 0; i < 16; i++) {
        int u = tid + i * 256;            // 0..4095
        int m  = u >> 5;                  // token 0..127 (same m across a warp)
        int k4 = u & 31;
        int idx = sidx[m];
        const float4 xv = *(const float4*)(x + (size_t)(m0 + m) * (GV * DV) + g * DV + k4 * 4);
        const float4 qv = __ldg((const float4*)(cbg + (size_t)idx * DV + k4 * 4));
        // quantized = xs + (q - xs), exactly as the reference computes it
        float4 o;
        o.x = __fadd_rn(xv.x, __fsub_rn(qv.x, xv.x));
        o.y = __fadd_rn(xv.y, __fsub_rn(qv.y, xv.y));
        o.z = __fadd_rn(xv.z, __fsub_rn(qv.z, xv.z));
        o.w = __fadd_rn(xv.w, __fsub_rn(qv.w, xv.w));
        *(float4*)(outq + (size_t)(m0 + m) * (GV * DV) + g * DV + k4 * 4) = o;
        float d = __fsub_rn(xv.x, qv.x); lacc = fmaf(d, d, lacc);
        d = __fsub_rn(xv.y, qv.y); lacc = fmaf(d, d, lacc);
        d = __fsub_rn(xv.z, qv.z); lacc = fmaf(d, d, lacc);
        d = __fsub_rn(xv.w, qv.w); lacc = fmaf(d, d, lacc);
    }
    #pragma unroll
    for (int o = 16; o > 0; o >>= 1) lacc += __shfl_xor_sync(0xffffffffu, lacc, o);
    if ((tid & 31) == 0) wsum[tid >> 5] = lacc;
    __syncthreads();
    if (tid == 0) {
        double t = 0.0;
        #pragma unroll
        for (int i = 0; i < 8; i++) t += (double)wsum[i];
        atomicAdd(&g_loss, t);
        __threadfence();
        unsigned int done = atomicAdd(&g_cnt, 1u);
        if (done == (unsigned int)(gridDim.x * gridDim.y) - 1u) {
            float L = (float)(g_loss * (1.0 / (double)QN));
            losses[0] = L;   // commitment_loss
            losses[1] = L;   // codebook_loss (identical value)
        }
    }
}

extern "C" void kernel_launch(void* const* d_in, const int* in_sizes, int n_in,
                              void* d_out, int out_size) {
    (void)in_sizes; (void)n_in; (void)out_size;
    const float* x  = (const float*)d_in[0];
    const float* cb = (const float*)d_in[1];
    float* out    = (float*)d_out;
    float* outq   = out;            // [16777216]
    float* losses = out + QN;       // [2]
    float* outidx = out + QN + 2;   // [131072]

    k_prep<<<256, 256>>>(cb);

    cudaFuncSetAttribute(k_main, cudaFuncAttributeMaxDynamicSharedMemorySize, SM_TOTAL);
    k_main<<<dim3(MV / 128, GV), 256, SM_TOTAL>>>(x, cb, outq, losses, outidx);
}